// round 13
// baseline (speedup 1.0000x reference)
#include <cuda_runtime.h>
#include <cstdint>

#define NNODES 100000
#define TT 7
#define KK 10
#define DD 7
#define OO 32
#define OP 16                         // 16 packed f32x2 outputs
#define BLOCK 128
#define GRID ((NNODES + BLOCK - 1) / BLOCK)   // 782
#define NODE_B 280                    // bytes per node per type
#define STRA 30                       // floats/node in bufA (28 data + 2 pad)
#define STRB 42                       // floats/node in bufB (natural)
#define NPART (GRID * 4)              // per-warp partial rows

// deterministic per-warp partials + completion counter (zero-init at module load)
__device__ float g_partial[NPART * OO];
__device__ unsigned int g_count;

__device__ __forceinline__ void cp8(uint32_t s, const void* g) {
    asm volatile("cp.async.ca.shared.global [%0], [%1], 8;\n" :: "r"(s), "l"(g));
}
__device__ __forceinline__ void cp_commit() { asm volatile("cp.async.commit_group;\n" ::: "memory"); }
template<int N> __device__ __forceinline__ void cp_wait() { asm volatile("cp.async.wait_group %0;\n" :: "n"(N) : "memory"); }

__device__ __forceinline__ unsigned long long pack2(float lo, float hi) {
    unsigned long long d;
    asm("mov.b64 %0, {%1, %2};" : "=l"(d) : "f"(lo), "f"(hi));
    return d;
}
__device__ __forceinline__ float2 unpack2(unsigned long long v) {
    float2 r;
    asm("mov.b64 {%0, %1}, %2;" : "=f"(r.x), "=f"(r.y) : "l"(v));
    return r;
}
__device__ __forceinline__ unsigned long long fma2(unsigned long long a, unsigned long long b, unsigned long long c) {
    unsigned long long d;
    asm("fma.rn.f32x2 %0, %1, %2, %3;" : "=l"(d) : "l"(a), "l"(b), "l"(c));
    return d;
}

// load 7 floats from smem with float2 vectorization; base is compile-time
__device__ __forceinline__ void load7(const float* xs, int base, float xv[DD]) {
    if ((base & 1) == 0) {
        const float2* p = (const float2*)(xs + base);
        float2 a = p[0], b = p[1], c = p[2];
        xv[0]=a.x; xv[1]=a.y; xv[2]=b.x; xv[3]=b.y; xv[4]=c.x; xv[5]=c.y;
        xv[6]=xs[base + 6];
    } else {
        xv[0]=xs[base];
        const float2* p = (const float2*)(xs + base + 1);
        float2 a = p[0], b = p[1], c = p[2];
        xv[1]=a.x; xv[2]=a.y; xv[3]=b.x; xv[4]=b.y; xv[5]=c.x; xv[6]=c.y;
    }
}

__global__ __launch_bounds__(BLOCK, 5) void hetgcn_fused(
    const float* __restrict__ x_node,      // [N, D]
    const float* __restrict__ x_het,       // [T, N, K, D]
    const int*   __restrict__ node_types,  // [N]
    const float* __restrict__ W_content,   // [T, D, D]
    const float* __restrict__ b_content,   // [T, D]
    const float* __restrict__ W_agg,       // [O, 56]
    const float* __restrict__ b_agg,       // [O]
    float* __restrict__ out)               // [O]
{
    __shared__ __align__(16) float bufA[BLOCK * STRA];          // 15360 B : k=0..3
    __shared__ __align__(16) float bufB[BLOCK * STRB];          // 21504 B : k=4..9
    __shared__ float sW[TT * DD * DD];                          // 1372 B
    __shared__ float sb[TT * DD];                               // 196 B
    __shared__ __align__(16) unsigned long long sWt2[(TT + 1) * DD * OP]; // 7168 B
    __shared__ int   s_last;

    const int tid = threadIdx.x;
    const int n0  = blockIdx.x * BLOCK;
    const int n   = n0 + tid;
    const bool active = (n < NNODES);
    const int rows = min(BLOCK, NNODES - n0);

    // ---- one-time weight staging (covered by first __syncthreads) ----
    for (int i = tid; i < TT * DD * DD; i += BLOCK) sW[i] = W_content[i];
    for (int i = tid; i < TT * DD;     i += BLOCK) sb[i] = b_content[i];
    for (int e = tid; e < 56 * OP; e += BLOCK) {   // sWt2[j*OP+p] = (W[2p][j], W[2p+1][j])
        int j = e >> 4, p = e & 15;
        sWt2[e] = pack2(W_agg[(2 * p) * 56 + j], W_agg[(2 * p + 1) * 56 + j]);
    }

    // ---- division-free staging precompute (ONCE per thread), 8B ops only ----
    const int m0A = tid / 14, offA = tid - m0A * 14;
    const int m0B = tid / 21, offB = tid - m0B * 21;
    const int iA_max = (tid < 112) ? ((rows - m0A + 7) >> 3) : 0;
    const int iB_max = (tid < 126) ? ((rows - m0B + 5) / 6)  : 0;

    const char* tile0 = (const char*)x_het + (size_t)n0 * NODE_B;
    const size_t type_stride = (size_t)NNODES * NODE_B;
    const uint32_t sAaddr = (uint32_t)__cvta_generic_to_shared(bufA) + m0A * (STRA * 4) + offA * 8;
    const uint32_t sBaddr = (uint32_t)__cvta_generic_to_shared(bufB) + m0B * (STRB * 4) + offB * 8;
    const int gA0 = m0A * NODE_B + offA * 8;
    const int gB0 = m0B * NODE_B + 112 + offB * 8;

    // prefetch A(0), B(0)
    {
        const char* gA = tile0 + gA0;
        #pragma unroll
        for (int i = 0; i < 16; ++i) if (i < iA_max) cp8(sAaddr + i * 960, gA + i * 2240);
        cp_commit();
        const char* gB = tile0 + gB0;
        #pragma unroll
        for (int i = 0; i < 22; ++i) if (i < iB_max) cp8(sBaddr + i * 1008, gB + i * 1680);
        cp_commit();
    }

    // packed output accumulators, init with bias
    unsigned long long z2[OP];
    {
        const float2* b2 = (const float2*)b_agg;
        #pragma unroll
        for (int p = 0; p < OP; ++p) {
            float2 b = __ldg(&b2[p]);
            z2[p] = pack2(b.x, b.y);
        }
    }

    #pragma unroll 1
    for (int t = 0; t < TT; ++t) {
        cp_wait<1>();            // A(t) landed (B(t) may still be in flight)
        __syncthreads();

        float Wr[DD * DD], br[DD];
        #pragma unroll
        for (int i = 0; i < DD * DD; ++i) Wr[i] = sW[t * DD * DD + i];
        #pragma unroll
        for (int i = 0; i < DD; ++i) br[i] = sb[t * DD + i];

        // zs = sum_k z ; za = sum_k |z| ;  sum_k leaky(z) = 0.505*zs + 0.495*za
        float zs[DD], za[DD];
        #pragma unroll
        for (int o = 0; o < DD; ++o) { zs[o] = 0.f; za[o] = 0.f; }

        // ---- k = 0..3 from bufA ----
        {
            const float* xs = &bufA[tid * STRA];
            #pragma unroll
            for (int k = 0; k < 4; ++k) {
                float xv[DD];
                load7(xs, k * DD, xv);
                #pragma unroll
                for (int o = 0; o < DD; ++o) {
                    float z = br[o];
                    #pragma unroll
                    for (int d = 0; d < DD; ++d) z = fmaf(xv[d], Wr[o * DD + d], z);
                    zs[o] += z;
                    za[o] += fabsf(z);
                }
            }
        }
        __syncthreads();         // done reading bufA

        if (t + 1 < TT) {        // prefetch A(t+1)
            const char* gA = tile0 + (size_t)(t + 1) * type_stride + gA0;
            #pragma unroll
            for (int i = 0; i < 16; ++i) if (i < iA_max) cp8(sAaddr + i * 960, gA + i * 2240);
            cp_commit();
            cp_wait<1>();        // B(t) landed (A(t+1) in flight)
        } else {
            cp_wait<0>();
        }
        __syncthreads();

        // ---- k = 4..9 from bufB ----
        {
            const float* xs = &bufB[tid * STRB];
            #pragma unroll
            for (int k = 0; k < 6; ++k) {
                float xv[DD];
                load7(xs, k * DD, xv);
                #pragma unroll
                for (int o = 0; o < DD; ++o) {
                    float z = br[o];
                    #pragma unroll
                    for (int d = 0; d < DD; ++d) z = fmaf(xv[d], Wr[o * DD + d], z);
                    zs[o] += z;
                    za[o] += fabsf(z);
                }
            }
        }
        __syncthreads();         // done reading bufB

        if (t + 1 < TT) {        // prefetch B(t+1)
            const char* gB = tile0 + (size_t)(t + 1) * type_stride + gB0;
            #pragma unroll
            for (int i = 0; i < 22; ++i) if (i < iB_max) cp8(sBaddr + i * 1008, gB + i * 1680);
            cp_commit();
        }

        // ---- stream this type's het segment into packed z accumulators ----
        // mean over k=10 folded in: 0.505/10 and 0.495/10
        const ulonglong2* wrow2 = (const ulonglong2*)&sWt2[t * DD * OP];
        #pragma unroll
        for (int j = 0; j < DD; ++j) {
            float a = fmaf(za[j], 0.0495f, zs[j] * 0.0505f);
            unsigned long long a2 = pack2(a, a);
            #pragma unroll
            for (int q = 0; q < OP / 2; ++q) {
                ulonglong2 w = wrow2[j * (OP / 2) + q];       // broadcast LDS.128
                z2[2 * q]     = fma2(a2, w.x, z2[2 * q]);
                z2[2 * q + 1] = fma2(a2, w.y, z2[2 * q + 1]);
            }
        }
    }

    // ---- self embedding (node's own type) streamed into z ----
    {
        const int ty = active ? node_types[n] : 0;
        float xn[DD];
        #pragma unroll
        for (int d = 0; d < DD; ++d) xn[d] = active ? x_node[n * DD + d] : 0.f;
        const ulonglong2* wrow2 = (const ulonglong2*)&sWt2[TT * DD * OP];
        #pragma unroll
        for (int o = 0; o < DD; ++o) {
            float z = sb[ty * DD + o];
            #pragma unroll
            for (int d = 0; d < DD; ++d) z = fmaf(xn[d], sW[ty * DD * DD + o * DD + d], z);
            float a = fmaxf(z, 0.01f * z);
            unsigned long long a2 = pack2(a, a);
            #pragma unroll
            for (int q = 0; q < OP / 2; ++q) {
                ulonglong2 w = wrow2[o * (OP / 2) + q];       // broadcast LDS.128
                z2[2 * q]     = fma2(a2, w.x, z2[2 * q]);
                z2[2 * q + 1] = fma2(a2, w.y, z2[2 * q + 1]);
            }
        }
    }

    // ---- sigmoid + warp butterfly; each lane keeps the o==lane sum ----
    const int wid = tid >> 5, lane = tid & 31;
    float myv = 0.f;
    #pragma unroll
    for (int p = 0; p < OP; ++p) {
        float2 v = unpack2(z2[p]);
        float y0 = active ? (1.f / (1.f + __expf(-v.x))) : 0.f;
        float y1 = active ? (1.f / (1.f + __expf(-v.y))) : 0.f;
        #pragma unroll
        for (int off = 16; off > 0; off >>= 1) {
            y0 += __shfl_xor_sync(0xffffffffu, y0, off);
            y1 += __shfl_xor_sync(0xffffffffu, y1, off);
        }
        if (lane == 2 * p)     myv = y0;
        if (lane == 2 * p + 1) myv = y1;
    }
    // per-warp partial row: one coalesced STG.32 per warp
    g_partial[(blockIdx.x * 4 + wid) * OO + lane] = myv;

    // ---- fused deterministic finale: last block reduces all partials ----
    __threadfence();
    __syncthreads();
    if (tid == 0) {
        unsigned int prev = atomicAdd(&g_count, 1u);
        s_last = (prev == (unsigned)(GRID - 1)) ? 1 : 0;
    }
    __syncthreads();
    if (s_last) {
        __threadfence();
        float* sfin = bufA;                    // reuse tile smem as scratch
        const volatile float* gp = g_partial;
        const int o = tid & 31;
        const int h = tid >> 5;                // 0..3
        float a0 = 0.f, a1 = 0.f, a2 = 0.f, a3 = 0.f;
        int b = h;
        for (; b + 12 < NPART; b += 16) {
            a0 += gp[(b     ) * OO + o];
            a1 += gp[(b +  4) * OO + o];
            a2 += gp[(b +  8) * OO + o];
            a3 += gp[(b + 12) * OO + o];
        }
        for (; b < NPART; b += 4) a0 += gp[b * OO + o];
        sfin[h * OO + o] = (a0 + a1) + (a2 + a3);
        __syncthreads();
        if (tid < OO)
            out[tid] = ((sfin[tid] + sfin[OO + tid]) + (sfin[2 * OO + tid] + sfin[3 * OO + tid]))
                       * (1.0f / (float)NNODES);
        if (tid == 0) g_count = 0;             // reset for next graph replay
    }
}

extern "C" void kernel_launch(void* const* d_in, const int* in_sizes, int n_in,
                              void* d_out, int out_size)
{
    const float* x_node    = (const float*)d_in[0];
    const float* x_het     = (const float*)d_in[1];
    const int*   types     = (const int*)  d_in[2];
    const float* W_content = (const float*)d_in[3];
    const float* b_content = (const float*)d_in[4];
    const float* W_agg     = (const float*)d_in[5];
    const float* b_agg     = (const float*)d_in[6];
    float* out = (float*)d_out;

    hetgcn_fused<<<GRID, BLOCK>>>(x_node, x_het, types, W_content, b_content,
                                  W_agg, b_agg, out);
}

// round 14
// speedup vs baseline: 1.3391x; 1.3391x over previous
#include <cuda_runtime.h>
#include <cstdint>

#define NNODES 100000
#define TT 7
#define KK 10
#define DD 7
#define OO 32
#define OP 16                         // 16 packed f32x2 outputs
#define BLOCK 128
#define GRID ((NNODES + BLOCK - 1) / BLOCK)   // 782
#define NODE_B 280                    // bytes per node per type
#define STRA 30                       // floats/node in bufA (28 data + 2 pad)
#define STRB 42                       // floats/node in bufB (natural)

// deterministic per-block partials + completion counter (zero-init at module load)
__device__ float g_partial[GRID * OO];
__device__ unsigned int g_count;

__device__ __forceinline__ void cp8(uint32_t s, const void* g) {
    asm volatile("cp.async.ca.shared.global [%0], [%1], 8;\n" :: "r"(s), "l"(g));
}
__device__ __forceinline__ void cp_commit() { asm volatile("cp.async.commit_group;\n" ::: "memory"); }
template<int N> __device__ __forceinline__ void cp_wait() { asm volatile("cp.async.wait_group %0;\n" :: "n"(N) : "memory"); }

__device__ __forceinline__ unsigned long long pack2(float lo, float hi) {
    unsigned long long d;
    asm("mov.b64 %0, {%1, %2};" : "=l"(d) : "f"(lo), "f"(hi));
    return d;
}
__device__ __forceinline__ float2 unpack2(unsigned long long v) {
    float2 r;
    asm("mov.b64 {%0, %1}, %2;" : "=f"(r.x), "=f"(r.y) : "l"(v));
    return r;
}
__device__ __forceinline__ unsigned long long fma2(unsigned long long a, unsigned long long b, unsigned long long c) {
    unsigned long long d;
    asm("fma.rn.f32x2 %0, %1, %2, %3;" : "=l"(d) : "l"(a), "l"(b), "l"(c));
    return d;
}

// load 7 floats from smem with float2 vectorization; base is compile-time
__device__ __forceinline__ void load7(const float* xs, int base, float xv[DD]) {
    if ((base & 1) == 0) {
        const float2* p = (const float2*)(xs + base);
        float2 a = p[0], b = p[1], c = p[2];
        xv[0]=a.x; xv[1]=a.y; xv[2]=b.x; xv[3]=b.y; xv[4]=c.x; xv[5]=c.y;
        xv[6]=xs[base + 6];
    } else {
        xv[0]=xs[base];
        const float2* p = (const float2*)(xs + base + 1);
        float2 a = p[0], b = p[1], c = p[2];
        xv[1]=a.x; xv[2]=a.y; xv[3]=b.x; xv[4]=b.y; xv[5]=c.x; xv[6]=c.y;
    }
}

// staging helpers: full (rows==BLOCK) path has no per-op predicates
__device__ __forceinline__ void stageA(uint32_t sAaddr, const char* gA,
                                       int tid, int iA_max, bool full) {
    if (full) {
        if (tid < 112) {
            #pragma unroll
            for (int i = 0; i < 16; ++i) cp8(sAaddr + i * 960, gA + i * 2240);
        }
    } else {
        #pragma unroll
        for (int i = 0; i < 16; ++i) if (i < iA_max) cp8(sAaddr + i * 960, gA + i * 2240);
    }
}
__device__ __forceinline__ void stageB(uint32_t sBaddr, const char* gB,
                                       int tid, int iB_max, bool full) {
    if (full) {
        if (tid < 126) {
            #pragma unroll
            for (int i = 0; i < 21; ++i) cp8(sBaddr + i * 1008, gB + i * 1680);
            if (21 < iB_max) cp8(sBaddr + 21 * 1008, gB + 21 * 1680);
        }
    } else {
        #pragma unroll
        for (int i = 0; i < 22; ++i) if (i < iB_max) cp8(sBaddr + i * 1008, gB + i * 1680);
    }
}

__global__ __launch_bounds__(BLOCK, 4) void hetgcn_fused(
    const float* __restrict__ x_node,      // [N, D]
    const float* __restrict__ x_het,       // [T, N, K, D]
    const int*   __restrict__ node_types,  // [N]
    const float* __restrict__ W_content,   // [T, D, D]
    const float* __restrict__ b_content,   // [T, D]
    const float* __restrict__ W_agg,       // [O, 56]
    const float* __restrict__ b_agg,       // [O]
    float* __restrict__ out)               // [O]
{
    __shared__ __align__(16) float bufA[BLOCK * STRA];          // 15360 B : k=0..3
    __shared__ __align__(16) float bufB[BLOCK * STRB];          // 21504 B : k=4..9
    __shared__ __align__(16) float sWb[TT * DD * 8];            // 1568 B : [W row(7), bias] packed
    __shared__ __align__(16) unsigned long long sWt2[(TT + 1) * DD * OP]; // 7168 B
    __shared__ float sY[4][OO];                                 // 512 B
    __shared__ int   s_last;

    const int tid = threadIdx.x;
    const int n0  = blockIdx.x * BLOCK;
    const int n   = n0 + tid;
    const bool active = (n < NNODES);
    const int rows = min(BLOCK, NNODES - n0);
    const bool full = (rows == BLOCK);

    // ---- one-time weight staging (covered by first __syncthreads) ----
    // packed rows: sWb[(t*7+o)*8 + d] = W[t][o][d] (d<7), [..+7] = b[t][o]
    if (tid < TT * DD) {
        #pragma unroll
        for (int d = 0; d < DD; ++d) sWb[tid * 8 + d] = W_content[tid * DD + d];
        sWb[tid * 8 + 7] = b_content[tid];
    }
    for (int e = tid; e < 56 * OP; e += BLOCK) {   // sWt2[j*OP+p] = (W[2p][j], W[2p+1][j])
        int j = e >> 4, p = e & 15;
        sWt2[e] = pack2(W_agg[(2 * p) * 56 + j], W_agg[(2 * p + 1) * 56 + j]);
    }

    // ---- division-free staging precompute (ONCE per thread), 8B ops only ----
    const int m0A = tid / 14, offA = tid - m0A * 14;
    const int m0B = tid / 21, offB = tid - m0B * 21;
    const int iA_max = (tid < 112) ? ((rows - m0A + 7) >> 3) : 0;
    const int iB_max = (tid < 126) ? ((rows - m0B + 5) / 6)  : 0;

    const char* tile0 = (const char*)x_het + (size_t)n0 * NODE_B;
    const size_t type_stride = (size_t)NNODES * NODE_B;
    const uint32_t sAaddr = (uint32_t)__cvta_generic_to_shared(bufA) + m0A * (STRA * 4) + offA * 8;
    const uint32_t sBaddr = (uint32_t)__cvta_generic_to_shared(bufB) + m0B * (STRB * 4) + offB * 8;
    const int gA0 = m0A * NODE_B + offA * 8;
    const int gB0 = m0B * NODE_B + 112 + offB * 8;

    // prefetch A(0), B(0)
    stageA(sAaddr, tile0 + gA0, tid, iA_max, full); cp_commit();
    stageB(sBaddr, tile0 + gB0, tid, iB_max, full); cp_commit();

    // packed output accumulators, init with bias
    unsigned long long z2[OP];
    {
        const float2* b2 = (const float2*)b_agg;
        #pragma unroll
        for (int p = 0; p < OP; ++p) {
            float2 b = __ldg(&b2[p]);
            z2[p] = pack2(b.x, b.y);
        }
    }

    #pragma unroll 1
    for (int t = 0; t < TT; ++t) {
        cp_wait<1>();            // A(t) landed (B(t) may still be in flight)
        __syncthreads();

        // type weights via LDS.128: 14 loads fill Wr[49] + br[7]
        float Wr[DD * DD], br[DD];
        {
            const float4* w4 = (const float4*)&sWb[t * DD * 8];
            #pragma unroll
            for (int o = 0; o < DD; ++o) {
                float4 a = w4[2 * o], b = w4[2 * o + 1];
                Wr[o * DD + 0] = a.x; Wr[o * DD + 1] = a.y;
                Wr[o * DD + 2] = a.z; Wr[o * DD + 3] = a.w;
                Wr[o * DD + 4] = b.x; Wr[o * DD + 5] = b.y;
                Wr[o * DD + 6] = b.z; br[o] = b.w;
            }
        }

        // zs = sum_k z ; za = sum_k |z| ;  sum_k leaky(z) = 0.505*zs + 0.495*za
        float zs[DD], za[DD];
        #pragma unroll
        for (int o = 0; o < DD; ++o) { zs[o] = 0.f; za[o] = 0.f; }

        // ---- k = 0..3 from bufA ----
        {
            const float* xs = &bufA[tid * STRA];
            #pragma unroll
            for (int k = 0; k < 4; ++k) {
                float xv[DD];
                load7(xs, k * DD, xv);
                #pragma unroll
                for (int o = 0; o < DD; ++o) {
                    float z = br[o];
                    #pragma unroll
                    for (int d = 0; d < DD; ++d) z = fmaf(xv[d], Wr[o * DD + d], z);
                    zs[o] += z;
                    za[o] += fabsf(z);
                }
            }
        }
        __syncthreads();         // done reading bufA

        if (t + 1 < TT) {        // prefetch A(t+1)
            stageA(sAaddr, tile0 + (size_t)(t + 1) * type_stride + gA0, tid, iA_max, full);
            cp_commit();
            cp_wait<1>();        // B(t) landed (A(t+1) in flight)
        } else {
            cp_wait<0>();
        }
        __syncthreads();

        // ---- k = 4..9 from bufB ----
        {
            const float* xs = &bufB[tid * STRB];
            #pragma unroll
            for (int k = 0; k < 6; ++k) {
                float xv[DD];
                load7(xs, k * DD, xv);
                #pragma unroll
                for (int o = 0; o < DD; ++o) {
                    float z = br[o];
                    #pragma unroll
                    for (int d = 0; d < DD; ++d) z = fmaf(xv[d], Wr[o * DD + d], z);
                    zs[o] += z;
                    za[o] += fabsf(z);
                }
            }
        }
        __syncthreads();         // done reading bufB

        if (t + 1 < TT) {        // prefetch B(t+1)
            stageB(sBaddr, tile0 + (size_t)(t + 1) * type_stride + gB0, tid, iB_max, full);
            cp_commit();
        }

        // ---- stream this type's het segment into packed z accumulators ----
        // mean over k=10 folded in: 0.505/10 and 0.495/10
        const ulonglong2* wrow2 = (const ulonglong2*)&sWt2[t * DD * OP];
        #pragma unroll
        for (int j = 0; j < DD; ++j) {
            float a = fmaf(za[j], 0.0495f, zs[j] * 0.0505f);
            unsigned long long a2 = pack2(a, a);
            #pragma unroll
            for (int q = 0; q < OP / 2; ++q) {
                ulonglong2 w = wrow2[j * (OP / 2) + q];       // broadcast LDS.128
                z2[2 * q]     = fma2(a2, w.x, z2[2 * q]);
                z2[2 * q + 1] = fma2(a2, w.y, z2[2 * q + 1]);
            }
        }
    }

    // ---- self embedding (node's own type) streamed into z ----
    {
        const int ty = active ? node_types[n] : 0;
        float xn[DD];
        #pragma unroll
        for (int d = 0; d < DD; ++d) xn[d] = active ? x_node[n * DD + d] : 0.f;
        const float4* w4 = (const float4*)&sWb[ty * DD * 8];
        const ulonglong2* wrow2 = (const ulonglong2*)&sWt2[TT * DD * OP];
        #pragma unroll
        for (int o = 0; o < DD; ++o) {
            float4 wa = w4[2 * o], wb = w4[2 * o + 1];
            float z = wb.w;
            z = fmaf(xn[0], wa.x, z); z = fmaf(xn[1], wa.y, z);
            z = fmaf(xn[2], wa.z, z); z = fmaf(xn[3], wa.w, z);
            z = fmaf(xn[4], wb.x, z); z = fmaf(xn[5], wb.y, z);
            z = fmaf(xn[6], wb.z, z);
            float a = fmaxf(z, 0.01f * z);
            unsigned long long a2 = pack2(a, a);
            #pragma unroll
            for (int q = 0; q < OP / 2; ++q) {
                ulonglong2 w = wrow2[o * (OP / 2) + q];       // broadcast LDS.128
                z2[2 * q]     = fma2(a2, w.x, z2[2 * q]);
                z2[2 * q + 1] = fma2(a2, w.y, z2[2 * q + 1]);
            }
        }
    }

    // ---- sigmoid + warp butterfly + per-block partial ----
    float y[OO];
    #pragma unroll
    for (int p = 0; p < OP; ++p) {
        float2 v = unpack2(z2[p]);
        y[2 * p]     = active ? (1.f / (1.f + __expf(-v.x))) : 0.f;
        y[2 * p + 1] = active ? (1.f / (1.f + __expf(-v.y))) : 0.f;
    }
    const int wid = tid >> 5, lane = tid & 31;
    #pragma unroll
    for (int o = 0; o < OO; ++o) {
        float v = y[o];
        #pragma unroll
        for (int off = 16; off > 0; off >>= 1)
            v += __shfl_xor_sync(0xffffffffu, v, off);
        if (lane == 0) sY[wid][o] = v;
    }
    __syncthreads();
    if (tid < OO)
        g_partial[blockIdx.x * OO + tid] =
            (sY[0][tid] + sY[1][tid]) + (sY[2][tid] + sY[3][tid]);

    // ---- fused deterministic finale: last block reduces all partials ----
    __threadfence();
    if (tid == 0) {
        unsigned int prev = atomicAdd(&g_count, 1u);
        s_last = (prev == (unsigned)(GRID - 1)) ? 1 : 0;
    }
    __syncthreads();
    if (s_last) {
        __threadfence();
        const volatile float* gp = g_partial;
        const int o = tid & 31;
        const int h = tid >> 5;                 // 0..3
        float a0 = 0.f, a1 = 0.f, a2 = 0.f, a3 = 0.f;
        int b = h;
        for (; b + 12 < GRID; b += 16) {
            a0 += gp[(b     ) * OO + o];
            a1 += gp[(b +  4) * OO + o];
            a2 += gp[(b +  8) * OO + o];
            a3 += gp[(b + 12) * OO + o];
        }
        for (; b < GRID; b += 4) a0 += gp[b * OO + o];
        sY[h][o] = (a0 + a1) + (a2 + a3);
        __syncthreads();
        if (tid < OO)
            out[tid] = ((sY[0][tid] + sY[1][tid]) + (sY[2][tid] + sY[3][tid]))
                       * (1.0f / (float)NNODES);
        if (tid == 0) g_count = 0;              // reset for next graph replay
    }
}

extern "C" void kernel_launch(void* const* d_in, const int* in_sizes, int n_in,
                              void* d_out, int out_size)
{
    const float* x_node    = (const float*)d_in[0];
    const float* x_het     = (const float*)d_in[1];
    const int*   types     = (const int*)  d_in[2];
    const float* W_content = (const float*)d_in[3];
    const float* b_content = (const float*)d_in[4];
    const float* W_agg     = (const float*)d_in[5];
    const float* b_agg     = (const float*)d_in[6];
    float* out = (float*)d_out;

    hetgcn_fused<<<GRID, BLOCK>>>(x_node, x_het, types, W_content, b_content,
                                  W_agg, b_agg, out);
}

// round 15
// speedup vs baseline: 1.3774x; 1.0286x over previous
#include <cuda_runtime.h>
#include <cstdint>

#define NNODES 100000
#define TT 7
#define KK 10
#define DD 7
#define OO 32
#define OP 16                         // 16 packed f32x2 outputs
#define BLOCK 128
#define GRID ((NNODES + BLOCK - 1) / BLOCK)   // 782
#define NODE_B 280                    // bytes per node per type
#define STRA 30                       // floats/node in bufA (28 data + 2 pad)
#define STRB 42                       // floats/node in bufB (natural)

// deterministic per-block partials + completion counter (zero-init at module load)
__device__ float g_partial[GRID * OO];
__device__ unsigned int g_count;

__device__ __forceinline__ void cp8(uint32_t s, const void* g) {
    asm volatile("cp.async.ca.shared.global [%0], [%1], 8;\n" :: "r"(s), "l"(g));
}
__device__ __forceinline__ void cp_commit() { asm volatile("cp.async.commit_group;\n" ::: "memory"); }
template<int N> __device__ __forceinline__ void cp_wait() { asm volatile("cp.async.wait_group %0;\n" :: "n"(N) : "memory"); }

__device__ __forceinline__ unsigned long long pack2(float lo, float hi) {
    unsigned long long d;
    asm("mov.b64 %0, {%1, %2};" : "=l"(d) : "f"(lo), "f"(hi));
    return d;
}
__device__ __forceinline__ float2 unpack2(unsigned long long v) {
    float2 r;
    asm("mov.b64 {%0, %1}, %2;" : "=f"(r.x), "=f"(r.y) : "l"(v));
    return r;
}
__device__ __forceinline__ unsigned long long fma2(unsigned long long a, unsigned long long b, unsigned long long c) {
    unsigned long long d;
    asm("fma.rn.f32x2 %0, %1, %2, %3;" : "=l"(d) : "l"(a), "l"(b), "l"(c));
    return d;
}

// load 7 floats from smem with float2 vectorization; base is compile-time
__device__ __forceinline__ void load7(const float* xs, int base, float xv[DD]) {
    if ((base & 1) == 0) {
        const float2* p = (const float2*)(xs + base);
        float2 a = p[0], b = p[1], c = p[2];
        xv[0]=a.x; xv[1]=a.y; xv[2]=b.x; xv[3]=b.y; xv[4]=c.x; xv[5]=c.y;
        xv[6]=xs[base + 6];
    } else {
        xv[0]=xs[base];
        const float2* p = (const float2*)(xs + base + 1);
        float2 a = p[0], b = p[1], c = p[2];
        xv[1]=a.x; xv[2]=a.y; xv[3]=b.x; xv[4]=b.y; xv[5]=c.x; xv[6]=c.y;
    }
}

__global__ __launch_bounds__(BLOCK, 4) void hetgcn_fused(
    const float* __restrict__ x_node,      // [N, D]
    const float* __restrict__ x_het,       // [T, N, K, D]
    const int*   __restrict__ node_types,  // [N]
    const float* __restrict__ W_content,   // [T, D, D]
    const float* __restrict__ b_content,   // [T, D]
    const float* __restrict__ W_agg,       // [O, 56]
    const float* __restrict__ b_agg,       // [O]
    float* __restrict__ out)               // [O]
{
    // warp-private tiles: warp w owns bufA[w]/bufB[w] (same totals as R12)
    __shared__ __align__(16) float bufA[4][32 * STRA];          // 15360 B : k=0..3
    __shared__ __align__(16) float bufB[4][32 * STRB];          // 21504 B : k=4..9
    __shared__ __align__(16) float sWb[TT * DD * 8];            // 1568 B : [W row(7), bias]
    __shared__ __align__(16) unsigned long long sWt2[(TT + 1) * DD * OP]; // 7168 B
    __shared__ float sY[4][OO];                                 // 512 B
    __shared__ int   s_last;

    const int tid  = threadIdx.x;
    const int wid  = tid >> 5;
    const int lane = tid & 31;
    const int n0   = blockIdx.x * BLOCK;
    const int n    = n0 + tid;
    // N % 32 == 0: a warp is fully active or fully inactive
    const bool wact = (n0 + wid * 32) < NNODES;

    // ---- one-time weight staging (block-wide; single __syncthreads below) ----
    if (tid < TT * DD) {
        #pragma unroll
        for (int d = 0; d < DD; ++d) sWb[tid * 8 + d] = W_content[tid * DD + d];
        sWb[tid * 8 + 7] = b_content[tid];
    }
    for (int e = tid; e < 56 * OP; e += BLOCK) {   // sWt2[j*OP+p] = (W[2p][j], W[2p+1][j])
        int j = e >> 4, p = e & 15;
        sWt2[e] = pack2(W_agg[(2 * p) * 56 + j], W_agg[(2 * p + 1) * 56 + j]);
    }

    // ---- warp-local division-free staging setup ----
    // A: lanes 0..27 -> 2 nodes/op (14 offsets each), 16 ops cover 32 nodes
    // B: lanes 0..20 -> 1 node/op (21 offsets),       32 ops cover 32 nodes
    const bool aAct = wact && (lane < 28);
    const int  m0   = lane / 14;                  // 0 or 1 (one div at setup)
    const int  offA = lane - 14 * m0;
    const bool bAct = wact && (lane < 21);

    const char*  wbase = (const char*)x_het + (size_t)(n0 + wid * 32) * NODE_B;
    const size_t tstride = (size_t)NNODES * NODE_B;
    const char*  gA = wbase + m0 * NODE_B + offA * 8;
    const char*  gB = wbase + 112 + lane * 8;
    const uint32_t sA = (uint32_t)__cvta_generic_to_shared(&bufA[wid][0]) + m0 * (STRA * 4) + offA * 8;
    const uint32_t sB = (uint32_t)__cvta_generic_to_shared(&bufB[wid][0]) + lane * 8;

    // prologue: stage A(0), B(0)
    if (aAct) {
        #pragma unroll
        for (int i = 0; i < 16; ++i) cp8(sA + i * (2 * STRA * 4), gA + i * (2 * NODE_B));
    }
    cp_commit();
    if (bAct) {
        #pragma unroll
        for (int i = 0; i < 32; ++i) cp8(sB + i * (STRB * 4), gB + i * NODE_B);
    }
    cp_commit();
    __syncthreads();   // weights visible; last block barrier before the tail

    // packed output accumulators, init with bias
    unsigned long long z2[OP];
    {
        const float2* b2 = (const float2*)b_agg;
        #pragma unroll
        for (int p = 0; p < OP; ++p) {
            float2 b = __ldg(&b2[p]);
            z2[p] = pack2(b.x, b.y);
        }
    }

    if (wact) {
        #pragma unroll 1
        for (int t = 0; t < TT; ++t) {
            cp_wait<1>();        // A(t) landed (B(t) may still be in flight)
            __syncwarp();

            // type weights via LDS.128: 14 loads fill Wr[49] + br[7]
            float Wr[DD * DD], br[DD];
            {
                const float4* w4 = (const float4*)&sWb[t * DD * 8];
                #pragma unroll
                for (int o = 0; o < DD; ++o) {
                    float4 a = w4[2 * o], b = w4[2 * o + 1];
                    Wr[o * DD + 0] = a.x; Wr[o * DD + 1] = a.y;
                    Wr[o * DD + 2] = a.z; Wr[o * DD + 3] = a.w;
                    Wr[o * DD + 4] = b.x; Wr[o * DD + 5] = b.y;
                    Wr[o * DD + 6] = b.z; br[o] = b.w;
                }
            }

            // zs = sum_k z ; za = sum_k |z| ; sum_k leaky(z) = 0.505*zs + 0.495*za
            float zs[DD], za[DD];
            #pragma unroll
            for (int o = 0; o < DD; ++o) { zs[o] = 0.f; za[o] = 0.f; }

            // ---- k = 0..3 from warp's bufA ----
            {
                const float* xs = &bufA[wid][lane * STRA];
                #pragma unroll
                for (int k = 0; k < 4; ++k) {
                    float xv[DD];
                    load7(xs, k * DD, xv);
                    #pragma unroll
                    for (int o = 0; o < DD; ++o) {
                        float z = br[o];
                        #pragma unroll
                        for (int d = 0; d < DD; ++d) z = fmaf(xv[d], Wr[o * DD + d], z);
                        zs[o] += z;
                        za[o] += fabsf(z);
                    }
                }
            }
            __syncwarp();        // warp done reading bufA

            if (t + 1 < TT) {    // stage A(t+1) into same warp buffer
                const char* g = gA + (size_t)(t + 1) * tstride;
                if (aAct) {
                    #pragma unroll
                    for (int i = 0; i < 16; ++i) cp8(sA + i * (2 * STRA * 4), g + i * (2 * NODE_B));
                }
                cp_commit();
                cp_wait<1>();    // B(t) landed (A(t+1) in flight)
            } else {
                cp_wait<0>();
            }
            __syncwarp();

            // ---- k = 4..9 from warp's bufB ----
            {
                const float* xs = &bufB[wid][lane * STRB];
                #pragma unroll
                for (int k = 0; k < 6; ++k) {
                    float xv[DD];
                    load7(xs, k * DD, xv);
                    #pragma unroll
                    for (int o = 0; o < DD; ++o) {
                        float z = br[o];
                        #pragma unroll
                        for (int d = 0; d < DD; ++d) z = fmaf(xv[d], Wr[o * DD + d], z);
                        zs[o] += z;
                        za[o] += fabsf(z);
                    }
                }
            }
            __syncwarp();        // warp done reading bufB

            if (t + 1 < TT) {    // stage B(t+1)
                const char* g = gB + (size_t)(t + 1) * tstride;
                if (bAct) {
                    #pragma unroll
                    for (int i = 0; i < 32; ++i) cp8(sB + i * (STRB * 4), g + i * NODE_B);
                }
                cp_commit();
            }

            // ---- stream this type's het segment into packed z accumulators ----
            // mean over k=10 folded in: 0.505/10 and 0.495/10
            const ulonglong2* wrow2 = (const ulonglong2*)&sWt2[t * DD * OP];
            #pragma unroll
            for (int j = 0; j < DD; ++j) {
                float a = fmaf(za[j], 0.0495f, zs[j] * 0.0505f);
                unsigned long long a2 = pack2(a, a);
                #pragma unroll
                for (int q = 0; q < OP / 2; ++q) {
                    ulonglong2 w = wrow2[j * (OP / 2) + q];   // broadcast LDS.128
                    z2[2 * q]     = fma2(a2, w.x, z2[2 * q]);
                    z2[2 * q + 1] = fma2(a2, w.y, z2[2 * q + 1]);
                }
            }
        }

        // ---- self embedding (node's own type) streamed into z ----
        {
            const int ty = node_types[n];
            float xn[DD];
            #pragma unroll
            for (int d = 0; d < DD; ++d) xn[d] = x_node[n * DD + d];
            const float4* w4 = (const float4*)&sWb[ty * DD * 8];
            const ulonglong2* wrow2 = (const ulonglong2*)&sWt2[TT * DD * OP];
            #pragma unroll
            for (int o = 0; o < DD; ++o) {
                float4 wa = w4[2 * o], wb = w4[2 * o + 1];
                float z = wb.w;
                z = fmaf(xn[0], wa.x, z); z = fmaf(xn[1], wa.y, z);
                z = fmaf(xn[2], wa.z, z); z = fmaf(xn[3], wa.w, z);
                z = fmaf(xn[4], wb.x, z); z = fmaf(xn[5], wb.y, z);
                z = fmaf(xn[6], wb.z, z);
                float a = fmaxf(z, 0.01f * z);
                unsigned long long a2 = pack2(a, a);
                #pragma unroll
                for (int q = 0; q < OP / 2; ++q) {
                    ulonglong2 w = wrow2[o * (OP / 2) + q];   // broadcast LDS.128
                    z2[2 * q]     = fma2(a2, w.x, z2[2 * q]);
                    z2[2 * q + 1] = fma2(a2, w.y, z2[2 * q + 1]);
                }
            }
        }

        // ---- sigmoid + warp butterfly ----
        #pragma unroll
        for (int p = 0; p < OP; ++p) {
            float2 v = unpack2(z2[p]);
            float y0 = 1.f / (1.f + __expf(-v.x));
            float y1 = 1.f / (1.f + __expf(-v.y));
            #pragma unroll
            for (int off = 16; off > 0; off >>= 1) {
                y0 += __shfl_xor_sync(0xffffffffu, y0, off);
                y1 += __shfl_xor_sync(0xffffffffu, y1, off);
            }
            if (lane == 0) { sY[wid][2 * p] = y0; sY[wid][2 * p + 1] = y1; }
        }
    } else {
        sY[wid][lane] = 0.f;     // inactive warp contributes zeros
    }
    __syncthreads();
    if (tid < OO)
        g_partial[blockIdx.x * OO + tid] =
            (sY[0][tid] + sY[1][tid]) + (sY[2][tid] + sY[3][tid]);

    // ---- fused deterministic finale: last block reduces all partials ----
    __threadfence();
    if (tid == 0) {
        unsigned int prev = atomicAdd(&g_count, 1u);
        s_last = (prev == (unsigned)(GRID - 1)) ? 1 : 0;
    }
    __syncthreads();
    if (s_last) {
        __threadfence();
        const volatile float* gp = g_partial;
        const int o = tid & 31;
        const int h = tid >> 5;                 // 0..3
        float a0 = 0.f, a1 = 0.f, a2 = 0.f, a3 = 0.f;
        int b = h;
        for (; b + 12 < GRID; b += 16) {
            a0 += gp[(b     ) * OO + o];
            a1 += gp[(b +  4) * OO + o];
            a2 += gp[(b +  8) * OO + o];
            a3 += gp[(b + 12) * OO + o];
        }
        for (; b < GRID; b += 4) a0 += gp[b * OO + o];
        sY[h][o] = (a0 + a1) + (a2 + a3);
        __syncthreads();
        if (tid < OO)
            out[tid] = ((sY[0][tid] + sY[1][tid]) + (sY[2][tid] + sY[3][tid]))
                       * (1.0f / (float)NNODES);
        if (tid == 0) g_count = 0;              // reset for next graph replay
    }
}

extern "C" void kernel_launch(void* const* d_in, const int* in_sizes, int n_in,
                              void* d_out, int out_size)
{
    const float* x_node    = (const float*)d_in[0];
    const float* x_het     = (const float*)d_in[1];
    const int*   types     = (const int*)  d_in[2];
    const float* W_content = (const float*)d_in[3];
    const float* b_content = (const float*)d_in[4];
    const float* W_agg     = (const float*)d_in[5];
    const float* b_agg     = (const float*)d_in[6];
    float* out = (float*)d_out;

    hetgcn_fused<<<GRID, BLOCK>>>(x_node, x_het, types, W_content, b_content,
                                  W_agg, b_agg, out);
}